// round 9
// baseline (speedup 1.0000x reference)
#include <cuda_runtime.h>
#include <math.h>
#include <stdint.h>

// Problem constants (B=32, S=512, H=2048, FP=SP=1024)
#define NTOK 16384
#define HDIM 2048
#define CDIM 1024
#define OUTW 2050

// int8 GEMM tiling: stage = 128 bytes of K per row (= 128 int8), SW128 swizzle
#define BM 128
#define BN 128
#define BKB 128                 // K-bytes per stage
#define KT (HDIM / BKB)         // 16 stages
#define SPLIT_SZ 16384          // 128 rows x 128 bytes
#define STAGE_SZ (4 * SPLIT_SZ) // Ah, Al, Bh, Bl = 64 KB
#define NSTAGE 3

// ---------------------------------------------------------------------------
// Scratch (allocation-free: __device__ globals)
// ---------------------------------------------------------------------------
__device__ float  g_logits[2][(size_t)NTOK * CDIM];
__device__ int8_t g_Ahi[2][(size_t)NTOK * HDIM];
__device__ int8_t g_Alo[2][(size_t)NTOK * HDIM];
__device__ int8_t g_Whi[2][(size_t)CDIM * HDIM];
__device__ int8_t g_Wlo[2][(size_t)CDIM * HDIM];
__device__ float  g_sA[2][NTOK];     // per compacted-row scale of A
__device__ float  g_sB[2][CDIM];     // per-row scale of W
__device__ int    g_list[2][NTOK];
__device__ int    g_cnt[2];
__device__ float  g_nonend[NTOK];

// ---------------------------------------------------------------------------
// helpers
// ---------------------------------------------------------------------------
__device__ __forceinline__ uint32_t smem_u32(const void* p) {
    uint32_t a;
    asm("{ .reg .u64 t; cvta.to.shared.u64 t, %1; cvt.u32.u64 %0, t; }" : "=r"(a) : "l"(p));
    return a;
}
__device__ __forceinline__ uint32_t swz128(uint32_t o) { return o ^ ((o >> 3) & 0x70); }
__device__ __forceinline__ void cp16(uint32_t dst, const void* src) {
    asm volatile("cp.async.cg.shared.global [%0], [%1], 16;" :: "r"(dst), "l"(src));
}
__device__ __forceinline__ void cp_commit() { asm volatile("cp.async.commit_group;" ::: "memory"); }
template <int N> __device__ __forceinline__ void cp_wait() {
    asm volatile("cp.async.wait_group %0;" :: "n"(N) : "memory");
}
__device__ __forceinline__ void ldsm4(uint32_t* r, uint32_t addr) {
    asm volatile("ldmatrix.sync.aligned.m8n8.x4.shared.b16 {%0,%1,%2,%3}, [%4];"
                 : "=r"(r[0]), "=r"(r[1]), "=r"(r[2]), "=r"(r[3]) : "r"(addr));
}
// s8 x s8 -> s32, m16n8k32
__device__ __forceinline__ void imma(int* c, const uint32_t* a, uint32_t b0, uint32_t b1) {
    asm volatile("mma.sync.aligned.m16n8k32.row.col.s32.s8.s8.s32 "
                 "{%0,%1,%2,%3}, {%4,%5,%6,%7}, {%8,%9}, {%0,%1,%2,%3};"
                 : "+r"(c[0]), "+r"(c[1]), "+r"(c[2]), "+r"(c[3])
                 : "r"(a[0]), "r"(a[1]), "r"(a[2]), "r"(a[3]), "r"(b0), "r"(b1));
}
__device__ __forceinline__ int q8(float x) {            // round-to-nearest int8
    return __float2int_rn(x);
}
// quantize float4 -> packed hi byte4 + lo byte4 (dual-level)
__device__ __forceinline__ void quant4(float4 v, float s, float inv_s,
                                       uint32_t& hi, uint32_t& lo) {
    int h0 = q8(v.x * inv_s), h1 = q8(v.y * inv_s);
    int h2 = q8(v.z * inv_s), h3 = q8(v.w * inv_s);
    float k = inv_s * 128.f;
    int l0 = q8((v.x - s * h0) * k), l1 = q8((v.y - s * h1) * k);
    int l2 = q8((v.z - s * h2) * k), l3 = q8((v.w - s * h3) * k);
    hi = (h0 & 0xff) | ((h1 & 0xff) << 8) | ((h2 & 0xff) << 16) | ((h3 & 0xff) << 24);
    lo = (l0 & 0xff) | ((l1 & 0xff) << 8) | ((l2 & 0xff) << 16) | ((l3 & 0xff) << 24);
}

// ---------------------------------------------------------------------------
// Kernel 0: reset counters
// ---------------------------------------------------------------------------
__global__ void k_reset() {
    if (threadIdx.x < 2) g_cnt[threadIdx.x] = 0;
}

// ---------------------------------------------------------------------------
// Kernel 1: end head + classification + list build + zero-fill + FUSED quant.
// One warp per token. Keeps the row in registers (64 floats/lane) across the
// dot product, absmax reduce and dual-level int8 quantization.
// ---------------------------------------------------------------------------
__global__ __launch_bounds__(256) void k_classify(
    const float* __restrict__ X, const int* __restrict__ pY,
    const float* __restrict__ W_end, const float* __restrict__ b_end,
    float* __restrict__ out)
{
    const int warp = threadIdx.x >> 5;
    const int lane = threadIdx.x & 31;
    const int t = blockIdx.x * 8 + warp;
    if (t >= NTOK) return;

    const float4* x4 = reinterpret_cast<const float4*>(X + (size_t)t * HDIM);
    const float4* w4 = reinterpret_cast<const float4*>(W_end);

    float4 v[16];
    float s = 0.f, m = 0.f;
    #pragma unroll
    for (int i = 0; i < 16; ++i) {
        float4 a = x4[lane + 32 * i];
        float4 b = w4[lane + 32 * i];
        v[i] = a;
        s += a.x * b.x + a.y * b.y + a.z * b.z + a.w * b.w;
        m = fmaxf(m, fmaxf(fmaxf(fabsf(a.x), fabsf(a.y)), fmaxf(fabsf(a.z), fabsf(a.w))));
    }
    #pragma unroll
    for (int o = 16; o; o >>= 1) {
        s += __shfl_xor_sync(0xffffffffu, s, o);
        m = fmaxf(m, __shfl_xor_sync(0xffffffffu, m, o));
    }
    const float logit = s + b_end[0];
    const float p = 1.f / (1.f + expf(-logit));
    if (lane == 0) g_nonend[t] = 1.f - p;

    const int c = pY[t];
    float* lp  = out;
    float* row = out + NTOK + (size_t)t * OUTW;

    int z0, z1, z2, z3;
    if (c == 0) {
        if (lane == 0) { lp[t] = logf(p); row[0] = p; row[1] = p; }
        z0 = 2; z1 = OUTW; z2 = 0; z3 = 0;
    } else if (c == 1 || c == 2) {
        const int z = c - 1;
        int q = 0;
        if (lane == 0) { q = atomicAdd(&g_cnt[z], 1); g_list[z][q] = t; }
        q = __shfl_sync(0xffffffffu, q, 0);
        const float sa = fmaxf(m, 1e-20f) * (1.f / 127.f);
        const float inv_sa = 1.f / sa;
        if (lane == 0) g_sA[z][q] = sa;
        uint32_t* dh = reinterpret_cast<uint32_t*>(g_Ahi[z] + (size_t)q * HDIM);
        uint32_t* dl = reinterpret_cast<uint32_t*>(g_Alo[z] + (size_t)q * HDIM);
        #pragma unroll
        for (int i = 0; i < 16; ++i) {
            uint32_t hi, lo;
            quant4(v[i], sa, inv_sa, hi, lo);
            dh[lane + 32 * i] = hi;
            dl[lane + 32 * i] = lo;
        }
        if (z == 0) { z0 = 0; z1 = 2; z2 = 2 + CDIM; z3 = OUTW; }
        else        { z0 = 0; z1 = 2 + CDIM; z2 = 0; z3 = 0; }
    } else {
        if (lane == 0) lp[t] = 0.f;
        z0 = 0; z1 = OUTW; z2 = 0; z3 = 0;
    }
    for (int i = z0 + lane; i < z1; i += 32) row[i] = 0.f;
    for (int i = z2 + lane; i < z3; i += 32) row[i] = 0.f;
}

// ---------------------------------------------------------------------------
// Kernel 1b: zero A pad rows [cnt, ceil128(cnt)), set their scale to 1.
// ---------------------------------------------------------------------------
__global__ __launch_bounds__(256) void k_padzero()
{
    const int z = blockIdx.y;
    const int cnt = g_cnt[z];
    const int pad = (cnt + BM - 1) & ~(BM - 1);
    const int warp = threadIdx.x >> 5, lane = threadIdx.x & 31;
    const int pos = cnt + blockIdx.x * 8 + warp;
    if (pos >= pad) return;
    if (lane == 0) g_sA[z][pos] = 1.f;
    uint32_t* dh = reinterpret_cast<uint32_t*>(g_Ahi[z] + (size_t)pos * HDIM);
    uint32_t* dl = reinterpret_cast<uint32_t*>(g_Alo[z] + (size_t)pos * HDIM);
    #pragma unroll
    for (int i = 0; i < 16; ++i) {
        dh[lane + 32 * i] = 0u;
        dl[lane + 32 * i] = 0u;
    }
}

// ---------------------------------------------------------------------------
// Kernel 2: dual-level int8 quantization of W rows. One warp per row.
// ---------------------------------------------------------------------------
__global__ __launch_bounds__(256) void k_convert_w(
    const float* __restrict__ W_hcw, const float* __restrict__ W_roo)
{
    const int z = blockIdx.y;
    const int warp = threadIdx.x >> 5, lane = threadIdx.x & 31;
    const int rowi = blockIdx.x * 8 + warp;
    if (rowi >= CDIM) return;
    const float* W = z ? W_roo : W_hcw;
    const float4* src = reinterpret_cast<const float4*>(W + (size_t)rowi * HDIM);

    float4 v[16];
    float m = 0.f;
    #pragma unroll
    for (int i = 0; i < 16; ++i) {
        float4 a = src[lane + 32 * i];
        v[i] = a;
        m = fmaxf(m, fmaxf(fmaxf(fabsf(a.x), fabsf(a.y)), fmaxf(fabsf(a.z), fabsf(a.w))));
    }
    #pragma unroll
    for (int o = 16; o; o >>= 1) m = fmaxf(m, __shfl_xor_sync(0xffffffffu, m, o));

    const float sb = fmaxf(m, 1e-20f) * (1.f / 127.f);
    const float inv_sb = 1.f / sb;
    if (lane == 0) g_sB[z][rowi] = sb;

    uint32_t* dh = reinterpret_cast<uint32_t*>(g_Whi[z] + (size_t)rowi * HDIM);
    uint32_t* dl = reinterpret_cast<uint32_t*>(g_Wlo[z] + (size_t)rowi * HDIM);
    #pragma unroll
    for (int i = 0; i < 16; ++i) {
        uint32_t hi, lo;
        quant4(v[i], sb, inv_sb, hi, lo);
        dh[lane + 32 * i] = hi;
        dl[lane + 32 * i] = lo;
    }
}

// ---------------------------------------------------------------------------
// Kernel 3: split-int8 GEMM via mma.sync.m16n8k32.s8 (IMMA, 2x bf16 rate).
// 128x128 CTA tile, 128-byte K-stages (SW128), 3-stage cp.async pipeline,
// single sync per K-iter. acc1 = hh, acc2 = hl + lh; dequant in epilogue.
// ---------------------------------------------------------------------------
__device__ __forceinline__ void load_stage(int z, int m0, int n0, int k0,
                                           uint32_t sbase, int tid)
{
    const int8_t* Ah = g_Ahi[z];
    const int8_t* Al = g_Alo[z];
    const int8_t* Bh = g_Whi[z];
    const int8_t* Bl = g_Wlo[z];
    #pragma unroll
    for (int i = 0; i < 4; ++i) {          // 1024 16B-chunks per operand-half
        int c = tid + 256 * i;
        int r = c >> 3, cc = c & 7;
        uint32_t off = swz128((uint32_t)(r * 128 + cc * 16));
        size_t ga = (size_t)(m0 + r) * HDIM + k0 + cc * 16;
        size_t gb = (size_t)(n0 + r) * HDIM + k0 + cc * 16;
        cp16(sbase + off,                Ah + ga);
        cp16(sbase + SPLIT_SZ + off,     Al + ga);
        cp16(sbase + 2 * SPLIT_SZ + off, Bh + gb);
        cp16(sbase + 3 * SPLIT_SZ + off, Bl + gb);
    }
}

__global__ __launch_bounds__(256, 1) void k_gemm_mma()
{
    extern __shared__ char dsm[];
    const int z   = blockIdx.z;
    const int cnt = g_cnt[z];
    const int m0  = blockIdx.y * BM;
    if (m0 >= cnt) return;
    const int n0  = blockIdx.x * BN;
    const int tid  = threadIdx.x;
    const int wid  = tid >> 5;
    const int lane = tid & 31;
    const int warpM = wid & 3;      // rows warpM*32 .. +31
    const int warpN = wid >> 2;     // cols warpN*64 .. +63

    uint32_t sb = (smem_u32(dsm) + 127u) & ~127u;

    int acc1[2][8][4], acc2[2][8][4];
    #pragma unroll
    for (int i = 0; i < 2; ++i)
        #pragma unroll
        for (int j = 0; j < 8; ++j)
            #pragma unroll
            for (int q = 0; q < 4; ++q) { acc1[i][j][q] = 0; acc2[i][j][q] = 0; }

    load_stage(z, m0, n0, 0,   sb,            tid); cp_commit();
    load_stage(z, m0, n0, BKB, sb + STAGE_SZ, tid); cp_commit();

    const int sub  = lane >> 3;
    const int lrow = lane & 7;
    // A: matrices (sub&1 -> row half, sub>>1 -> 16-byte k half)
    const int a_row = warpM * 32 + (sub & 1) * 8 + lrow;
    const int a_kb  = (sub >> 1) * 16;
    // B: matrices (sub>>1 -> n half, sub&1 -> 16-byte k half)
    const int b_row = warpN * 64 + (sub >> 1) * 8 + lrow;
    const int b_kb  = (sub & 1) * 16;

    for (int kt = 0; kt < KT; ++kt) {
        if (kt == KT - 1) cp_wait<0>(); else cp_wait<1>();
        __syncthreads();
        if (kt + 2 < KT) {
            load_stage(z, m0, n0, (kt + 2) * BKB, sb + ((kt + 2) % NSTAGE) * STAGE_SZ, tid);
            cp_commit();
        }
        const uint32_t st = sb + (kt % NSTAGE) * STAGE_SZ;

        #pragma unroll
        for (int s = 0; s < 4; ++s) {       // four k32 steps per 128B stage
            const int kb = s * 32;
            uint32_t Af[2][2][4];           // [split][mtile][4]
            uint32_t Bf[2][4][4];           // [split][n16 tile][4]
            #pragma unroll
            for (int i = 0; i < 2; ++i) {
                uint32_t off = swz128((uint32_t)((a_row + i * 16) * 128 + kb + a_kb));
                ldsm4(Af[0][i], st + off);
                ldsm4(Af[1][i], st + SPLIT_SZ + off);
            }
            #pragma unroll
            for (int j = 0; j < 4; ++j) {
                uint32_t off = swz128((uint32_t)((b_row + j * 16) * 128 + kb + b_kb));
                ldsm4(Bf[0][j], st + 2 * SPLIT_SZ + off);
                ldsm4(Bf[1][j], st + 3 * SPLIT_SZ + off);
            }
            #pragma unroll
            for (int i = 0; i < 2; ++i)
                #pragma unroll
                for (int j = 0; j < 8; ++j) {
                    const uint32_t bh0 = Bf[0][j >> 1][(j & 1) * 2];
                    const uint32_t bh1 = Bf[0][j >> 1][(j & 1) * 2 + 1];
                    const uint32_t bl0 = Bf[1][j >> 1][(j & 1) * 2];
                    const uint32_t bl1 = Bf[1][j >> 1][(j & 1) * 2 + 1];
                    imma(acc1[i][j], Af[0][i], bh0, bh1);   // hi*hi
                    imma(acc2[i][j], Af[0][i], bl0, bl1);   // hi*lo
                    imma(acc2[i][j], Af[1][i], bh0, bh1);   // lo*hi
                }
        }
    }

    // epilogue: dequant = sA[row] * sB[col] * (acc1 + acc2/128)
    const int g = lane >> 2, tq = lane & 3;
    float* Lg = g_logits[z];
    const float* sAz = g_sA[z];
    const float* sBz = g_sB[z];
    #pragma unroll
    for (int i = 0; i < 2; ++i) {
        const int r0 = m0 + warpM * 32 + i * 16 + g;
        const float sa0 = sAz[r0], sa1 = sAz[r0 + 8];
        #pragma unroll
        for (int j = 0; j < 8; ++j) {
            const int col = n0 + warpN * 64 + j * 8 + 2 * tq;
            const float sb0 = sBz[col], sb1 = sBz[col + 1];
            const float f0 = ((float)acc1[i][j][0] + (float)acc2[i][j][0] * 0.0078125f) * sa0 * sb0;
            const float f1 = ((float)acc1[i][j][1] + (float)acc2[i][j][1] * 0.0078125f) * sa0 * sb1;
            const float f2 = ((float)acc1[i][j][2] + (float)acc2[i][j][2] * 0.0078125f) * sa1 * sb0;
            const float f3 = ((float)acc1[i][j][3] + (float)acc2[i][j][3] * 0.0078125f) * sa1 * sb1;
            if (r0 < cnt)
                *reinterpret_cast<float2*>(Lg + (size_t)r0 * CDIM + col) = make_float2(f0, f1);
            if (r0 + 8 < cnt)
                *reinterpret_cast<float2*>(Lg + (size_t)(r0 + 8) * CDIM + col) = make_float2(f2, f3);
        }
    }
}

// ---------------------------------------------------------------------------
// Kernel 4: softmax + scale by non_end + scatter + log_prob.
// ---------------------------------------------------------------------------
__global__ __launch_bounds__(256) void k_softmax(
    const int* __restrict__ Y,
    const float* __restrict__ b_hcw, const float* __restrict__ b_roo,
    float* __restrict__ out)
{
    const int z    = blockIdx.z;
    const int warp = threadIdx.x >> 5;
    const int lane = threadIdx.x & 31;
    const int pos  = blockIdx.x * 8 + warp;
    if (pos >= g_cnt[z]) return;
    const int t = g_list[z][pos];

    const float* __restrict__ bias = (z == 0) ? b_hcw : b_roo;
    const float* Lrow = g_logits[z] + (size_t)pos * CDIM;
    const float4* L4 = reinterpret_cast<const float4*>(Lrow);
    const float4* B4 = reinterpret_cast<const float4*>(bias);

    float4 v[8];
    float mx = -1e30f;
    #pragma unroll
    for (int i = 0; i < 8; ++i) {
        float4 a = L4[lane + 32 * i];
        float4 b = B4[lane + 32 * i];
        a.x += b.x; a.y += b.y; a.z += b.z; a.w += b.w;
        v[i] = a;
        mx = fmaxf(mx, fmaxf(fmaxf(a.x, a.y), fmaxf(a.z, a.w)));
    }
    #pragma unroll
    for (int o = 16; o; o >>= 1) mx = fmaxf(mx, __shfl_xor_sync(0xffffffffu, mx, o));

    float sum = 0.f;
    #pragma unroll
    for (int i = 0; i < 8; ++i) {
        v[i].x = expf(v[i].x - mx); v[i].y = expf(v[i].y - mx);
        v[i].z = expf(v[i].z - mx); v[i].w = expf(v[i].w - mx);
        sum += (v[i].x + v[i].y) + (v[i].z + v[i].w);
    }
    #pragma unroll
    for (int o = 16; o; o >>= 1) sum += __shfl_xor_sync(0xffffffffu, sum, o);

    const float ne = g_nonend[t];
    const float scale = ne / sum;

    float* row = out + NTOK + (size_t)t * OUTW + ((z == 0) ? 2 : 2 + CDIM);
    #pragma unroll
    for (int i = 0; i < 8; ++i) {
        const int c0 = 4 * (lane + 32 * i);
        *reinterpret_cast<float2*>(row + c0)     = make_float2(v[i].x * scale, v[i].y * scale);
        *reinterpret_cast<float2*>(row + c0 + 2) = make_float2(v[i].z * scale, v[i].w * scale);
    }

    if (lane == 0) {
        const int yv = Y[t];
        int idx = yv - 2 - ((z == 0) ? 0 : CDIM);
        idx = min(max(idx, 0), CDIM - 1);
        const float li = Lrow[idx] + bias[idx];
        out[t] = (li - mx) - logf(sum) + logf(ne);
    }
}

// ---------------------------------------------------------------------------
// Launcher
// ---------------------------------------------------------------------------
extern "C" void kernel_launch(void* const* d_in, const int* in_sizes, int n_in,
                              void* d_out, int out_size)
{
    const float* X     = (const float*)d_in[0];
    const int*   pY    = (const int*)d_in[1];
    const int*   Y     = (const int*)d_in[2];
    const float* W_end = (const float*)d_in[3];
    const float* b_end = (const float*)d_in[4];
    const float* W_hcw = (const float*)d_in[5];
    const float* b_hcw = (const float*)d_in[6];
    const float* W_roo = (const float*)d_in[7];
    const float* b_roo = (const float*)d_in[8];
    float* out = (float*)d_out;
    (void)in_sizes; (void)n_in; (void)out_size;

    const int dyn = 128 + NSTAGE * STAGE_SZ;   // 196736
    static bool attr_set = false;
    if (!attr_set) {
        cudaFuncSetAttribute(k_gemm_mma, cudaFuncAttributeMaxDynamicSharedMemorySize, dyn);
        attr_set = true;
    }

    k_reset<<<1, 32>>>();
    k_classify<<<NTOK / 8, 256>>>(X, pY, W_end, b_end, out);
    k_padzero<<<dim3(16, 2), 256>>>();
    k_convert_w<<<dim3(CDIM / 8, 2), 256>>>(W_hcw, W_roo);
    k_gemm_mma<<<dim3(CDIM / BN, NTOK / BM, 2), 256, dyn>>>();
    k_softmax<<<dim3(NTOK / 8, 1, 2), 256>>>(Y, b_hcw, b_roo, out);
}

// round 10
// speedup vs baseline: 2.6470x; 2.6470x over previous
#include <cuda_runtime.h>
#include <cuda_bf16.h>
#include <math.h>
#include <stdint.h>

// Problem constants (B=32, S=512, H=2048, FP=SP=1024)
#define NTOK 16384
#define HDIM 2048
#define CDIM 1024
#define OUTW 2050

// GEMM tiling (mma.sync path)
#define BM 128
#define BN 128
#define BK 64                   // bf16 elems per K-stage = 128 bytes/row
#define KT (HDIM / BK)          // 32
#define SPLIT_SZ 16384          // 128 rows x 128 bytes
#define STAGE_SZ (4 * SPLIT_SZ) // Ah, Al, Bh, Bl = 64 KB
#define NSTAGE 3

// ---------------------------------------------------------------------------
// Scratch (allocation-free: __device__ globals)
// ---------------------------------------------------------------------------
__device__ float g_logits[2][(size_t)NTOK * CDIM];
__device__ __nv_bfloat16 g_Ahi[2][(size_t)NTOK * HDIM];
__device__ __nv_bfloat16 g_Alo[2][(size_t)NTOK * HDIM];
__device__ __nv_bfloat16 g_Whi[2][(size_t)CDIM * HDIM];
__device__ __nv_bfloat16 g_Wlo[2][(size_t)CDIM * HDIM];
__device__ int   g_list[2][NTOK];
__device__ int   g_cnt[2];
__device__ float g_nonend[NTOK];

// ---------------------------------------------------------------------------
// helpers
// ---------------------------------------------------------------------------
__device__ __forceinline__ uint32_t smem_u32(const void* p) {
    uint32_t a;
    asm("{ .reg .u64 t; cvta.to.shared.u64 t, %1; cvt.u32.u64 %0, t; }" : "=r"(a) : "l"(p));
    return a;
}
__device__ __forceinline__ uint32_t swz128(uint32_t o) { return o ^ ((o >> 3) & 0x70); }
__device__ __forceinline__ void cp16(uint32_t dst, const void* src) {
    asm volatile("cp.async.cg.shared.global [%0], [%1], 16;" :: "r"(dst), "l"(src));
}
__device__ __forceinline__ void cp_commit() { asm volatile("cp.async.commit_group;" ::: "memory"); }
template <int N> __device__ __forceinline__ void cp_wait() {
    asm volatile("cp.async.wait_group %0;" :: "n"(N) : "memory");
}
__device__ __forceinline__ void ldsm4(uint32_t* r, uint32_t addr) {
    asm volatile("ldmatrix.sync.aligned.m8n8.x4.shared.b16 {%0,%1,%2,%3}, [%4];"
                 : "=r"(r[0]), "=r"(r[1]), "=r"(r[2]), "=r"(r[3]) : "r"(addr));
}
__device__ __forceinline__ void hmma(float* c, const uint32_t* a, uint32_t b0, uint32_t b1) {
    asm volatile("mma.sync.aligned.m16n8k16.row.col.f32.bf16.bf16.f32 "
                 "{%0,%1,%2,%3}, {%4,%5,%6,%7}, {%8,%9}, {%0,%1,%2,%3};"
                 : "+f"(c[0]), "+f"(c[1]), "+f"(c[2]), "+f"(c[3])
                 : "r"(a[0]), "r"(a[1]), "r"(a[2]), "r"(a[3]), "r"(b0), "r"(b1));
}
__device__ __forceinline__ void split2(float a, float b, uint32_t& hi, uint32_t& lo) {
    __nv_bfloat162 h = __floats2bfloat162_rn(a, b);
    float2 hf = __bfloat1622float2(h);
    __nv_bfloat162 l = __floats2bfloat162_rn(a - hf.x, b - hf.y);
    hi = *reinterpret_cast<uint32_t*>(&h);
    lo = *reinterpret_cast<uint32_t*>(&l);
}

// ---------------------------------------------------------------------------
// Kernel 0: reset counters
// ---------------------------------------------------------------------------
__global__ void k_reset() {
    if (threadIdx.x < 2) g_cnt[threadIdx.x] = 0;
}

// ---------------------------------------------------------------------------
// Kernel 1: end head + classification + list build + zero-fill + FUSED X-split.
// ---------------------------------------------------------------------------
__global__ __launch_bounds__(256) void k_classify(
    const float* __restrict__ X, const int* __restrict__ pY,
    const float* __restrict__ W_end, const float* __restrict__ b_end,
    float* __restrict__ out)
{
    const int warp = threadIdx.x >> 5;
    const int lane = threadIdx.x & 31;
    const int t = blockIdx.x * 8 + warp;
    if (t >= NTOK) return;

    const float4* x4 = reinterpret_cast<const float4*>(X + (size_t)t * HDIM);
    const float4* w4 = reinterpret_cast<const float4*>(W_end);
    float s = 0.f;
    #pragma unroll
    for (int i = 0; i < 16; ++i) {
        float4 a = x4[lane + 32 * i];
        float4 b = w4[lane + 32 * i];
        s += a.x * b.x + a.y * b.y + a.z * b.z + a.w * b.w;
    }
    #pragma unroll
    for (int o = 16; o; o >>= 1) s += __shfl_xor_sync(0xffffffffu, s, o);
    const float logit = s + b_end[0];
    const float p = 1.f / (1.f + expf(-logit));

    if (lane == 0) g_nonend[t] = 1.f - p;

    const int c = pY[t];
    float* lp  = out;
    float* row = out + NTOK + (size_t)t * OUTW;

    int z0, z1, z2, z3;
    if (c == 0) {
        if (lane == 0) { lp[t] = logf(p); row[0] = p; row[1] = p; }
        z0 = 2; z1 = OUTW; z2 = 0; z3 = 0;
    } else if (c == 1 || c == 2) {
        const int z = c - 1;
        int q = 0;
        if (lane == 0) { q = atomicAdd(&g_cnt[z], 1); g_list[z][q] = t; }
        q = __shfl_sync(0xffffffffu, q, 0);
        uint2* dh = reinterpret_cast<uint2*>(g_Ahi[z] + (size_t)q * HDIM);
        uint2* dl = reinterpret_cast<uint2*>(g_Alo[z] + (size_t)q * HDIM);
        #pragma unroll
        for (int i = 0; i < 16; ++i) {
            float4 v = x4[lane + 32 * i];
            uint32_t h0, l0, h1, l1;
            split2(v.x, v.y, h0, l0);
            split2(v.z, v.w, h1, l1);
            dh[lane + 32 * i] = make_uint2(h0, h1);
            dl[lane + 32 * i] = make_uint2(l0, l1);
        }
        if (z == 0) { z0 = 0; z1 = 2; z2 = 2 + CDIM; z3 = OUTW; }
        else        { z0 = 0; z1 = 2 + CDIM; z2 = 0; z3 = 0; }
    } else {
        if (lane == 0) lp[t] = 0.f;
        z0 = 0; z1 = OUTW; z2 = 0; z3 = 0;
    }
    for (int i = z0 + lane; i < z1; i += 32) row[i] = 0.f;
    for (int i = z2 + lane; i < z3; i += 32) row[i] = 0.f;
}

// ---------------------------------------------------------------------------
// Kernel 2: MERGED weight split (blocks [0,256)) + A pad-row zeroing
// (blocks [256,272)). Runs after k_classify (pad part needs g_cnt).
// ---------------------------------------------------------------------------
__global__ __launch_bounds__(256) void k_convert_w_pad(
    const float* __restrict__ W_hcw, const float* __restrict__ W_roo)
{
    const int z = blockIdx.y;
    const int warp = threadIdx.x >> 5, lane = threadIdx.x & 31;

    if (blockIdx.x < 2 * CDIM / 8) {
        // --- weight split: half-row per warp ---
        const int half = blockIdx.x * 8 + warp;        // 0 .. 2*CDIM-1
        const int rowi = half >> 1;
        const int off  = (half & 1) * 256;             // float4 offset within row
        const float* W = z ? W_roo : W_hcw;
        const float4* s = reinterpret_cast<const float4*>(W + (size_t)rowi * HDIM) + off;
        uint2* dh = reinterpret_cast<uint2*>(g_Whi[z] + (size_t)rowi * HDIM) + off;
        uint2* dl = reinterpret_cast<uint2*>(g_Wlo[z] + (size_t)rowi * HDIM) + off;
        #pragma unroll
        for (int i = 0; i < 8; ++i) {
            float4 v = s[lane + 32 * i];
            uint32_t h0, l0, h1, l1;
            split2(v.x, v.y, h0, l0);
            split2(v.z, v.w, h1, l1);
            dh[lane + 32 * i] = make_uint2(h0, h1);
            dl[lane + 32 * i] = make_uint2(l0, l1);
        }
    } else {
        // --- zero A pad rows [cnt, ceil128(cnt)) ---
        const int cnt = g_cnt[z];
        const int pad = (cnt + BM - 1) & ~(BM - 1);
        const int pos = cnt + (blockIdx.x - 2 * CDIM / 8) * 8 + warp;
        if (pos >= pad) return;
        uint2* dh = reinterpret_cast<uint2*>(g_Ahi[z] + (size_t)pos * HDIM);
        uint2* dl = reinterpret_cast<uint2*>(g_Alo[z] + (size_t)pos * HDIM);
        #pragma unroll
        for (int i = 0; i < 16; ++i) {
            dh[lane + 32 * i] = make_uint2(0u, 0u);
            dl[lane + 32 * i] = make_uint2(0u, 0u);
        }
    }
}

// ---------------------------------------------------------------------------
// Kernel 3: split-bf16 GEMM via mma.sync.m16n8k16 (HMMA).  [R5 best config]
// 128x128 CTA tile, BK=64, 3-stage cp.async pipeline, single sync per K-iter,
// explicit fragment double-buffering across s-steps.
// ---------------------------------------------------------------------------
__device__ __forceinline__ void load_stage(int z, int m0, int n0, int k0,
                                           uint32_t sbase, int tid)
{
    const __nv_bfloat16* Ah = g_Ahi[z];
    const __nv_bfloat16* Al = g_Alo[z];
    const __nv_bfloat16* Bh = g_Whi[z];
    const __nv_bfloat16* Bl = g_Wlo[z];
    #pragma unroll
    for (int i = 0; i < 4; ++i) {
        int c = tid + 256 * i;
        int r = c >> 3, cc = c & 7;
        uint32_t off = swz128((uint32_t)(r * 128 + cc * 16));
        size_t ga = (size_t)(m0 + r) * HDIM + k0 + cc * 8;
        size_t gb = (size_t)(n0 + r) * HDIM + k0 + cc * 8;
        cp16(sbase + off,                Ah + ga);
        cp16(sbase + SPLIT_SZ + off,     Al + ga);
        cp16(sbase + 2 * SPLIT_SZ + off, Bh + gb);
        cp16(sbase + 3 * SPLIT_SZ + off, Bl + gb);
    }
}

__device__ __forceinline__ void load_frags(
    uint32_t Af[2][2][4], uint32_t Bf[2][4][4], uint32_t st, int kb,
    int a_row, int a_kb, int b_row, int b_kb)
{
    #pragma unroll
    for (int i = 0; i < 2; ++i) {
        uint32_t off = swz128((uint32_t)((a_row + i * 16) * 128 + kb + a_kb));
        ldsm4(Af[0][i], st + off);
        ldsm4(Af[1][i], st + SPLIT_SZ + off);
    }
    #pragma unroll
    for (int j = 0; j < 4; ++j) {
        uint32_t off = swz128((uint32_t)((b_row + j * 16) * 128 + kb + b_kb));
        ldsm4(Bf[0][j], st + 2 * SPLIT_SZ + off);
        ldsm4(Bf[1][j], st + 3 * SPLIT_SZ + off);
    }
}

__device__ __forceinline__ void mma_block(
    float acc[2][8][4], uint32_t Af[2][2][4], uint32_t Bf[2][4][4])
{
    #pragma unroll
    for (int i = 0; i < 2; ++i)
        #pragma unroll
        for (int j = 0; j < 8; ++j) {
            const uint32_t bh0 = Bf[0][j >> 1][(j & 1) * 2];
            const uint32_t bh1 = Bf[0][j >> 1][(j & 1) * 2 + 1];
            const uint32_t bl0 = Bf[1][j >> 1][(j & 1) * 2];
            const uint32_t bl1 = Bf[1][j >> 1][(j & 1) * 2 + 1];
            hmma(acc[i][j], Af[0][i], bh0, bh1);   // hi*hi
            hmma(acc[i][j], Af[0][i], bl0, bl1);   // hi*lo
            hmma(acc[i][j], Af[1][i], bh0, bh1);   // lo*hi
        }
}

__global__ __launch_bounds__(256, 1) void k_gemm_mma()
{
    extern __shared__ char dsm[];
    const int z   = blockIdx.z;
    const int cnt = g_cnt[z];
    const int m0  = blockIdx.y * BM;
    if (m0 >= cnt) return;
    const int n0  = blockIdx.x * BN;
    const int tid  = threadIdx.x;
    const int wid  = tid >> 5;
    const int lane = tid & 31;
    const int warpM = wid & 3;
    const int warpN = wid >> 2;

    uint32_t sb = (smem_u32(dsm) + 127u) & ~127u;

    float acc[2][8][4];
    #pragma unroll
    for (int i = 0; i < 2; ++i)
        #pragma unroll
        for (int j = 0; j < 8; ++j)
            #pragma unroll
            for (int q = 0; q < 4; ++q) acc[i][j][q] = 0.f;

    load_stage(z, m0, n0, 0,  sb,            tid); cp_commit();
    load_stage(z, m0, n0, BK, sb + STAGE_SZ, tid); cp_commit();

    const int sub  = lane >> 3;
    const int lrow = lane & 7;
    const int a_row = warpM * 32 + (sub & 1) * 8 + lrow;
    const int a_kb  = (sub >> 1) * 16;
    const int b_row = warpN * 64 + (sub >> 1) * 8 + lrow;
    const int b_kb  = (sub & 1) * 16;

    uint32_t Af[2][2][2][4];   // [buf][split][mtile][4]
    uint32_t Bf[2][2][4][4];   // [buf][split][ntile][4]

    for (int kt = 0; kt < KT; ++kt) {
        if (kt >= KT - 1) cp_wait<0>(); else cp_wait<1>();
        __syncthreads();
        if (kt + 2 < KT) {
            load_stage(z, m0, n0, (kt + 2) * BK, sb + ((kt + 2) % NSTAGE) * STAGE_SZ, tid);
            cp_commit();
        }
        const uint32_t st = sb + (kt % NSTAGE) * STAGE_SZ;

        load_frags(Af[0], Bf[0], st, 0, a_row, a_kb, b_row, b_kb);
        #pragma unroll
        for (int s = 0; s < 4; ++s) {
            const int cur = s & 1;
            if (s < 3)
                load_frags(Af[cur ^ 1], Bf[cur ^ 1], st, (s + 1) * 32,
                           a_row, a_kb, b_row, b_kb);
            mma_block(acc, Af[cur], Bf[cur]);
        }
    }

    const int g = lane >> 2, tq = lane & 3;
    float* Lg = g_logits[z];
    #pragma unroll
    for (int i = 0; i < 2; ++i) {
        const int r0 = m0 + warpM * 32 + i * 16 + g;
        #pragma unroll
        for (int j = 0; j < 8; ++j) {
            const int col = n0 + warpN * 64 + j * 8 + 2 * tq;
            if (r0 < cnt)
                *reinterpret_cast<float2*>(Lg + (size_t)r0 * CDIM + col) =
                    make_float2(acc[i][j][0], acc[i][j][1]);
            if (r0 + 8 < cnt)
                *reinterpret_cast<float2*>(Lg + (size_t)(r0 + 8) * CDIM + col) =
                    make_float2(acc[i][j][2], acc[i][j][3]);
        }
    }
}

// ---------------------------------------------------------------------------
// Kernel 4: softmax + scale by non_end + scatter + log_prob.
// ---------------------------------------------------------------------------
__global__ __launch_bounds__(256) void k_softmax(
    const int* __restrict__ Y,
    const float* __restrict__ b_hcw, const float* __restrict__ b_roo,
    float* __restrict__ out)
{
    const int z    = blockIdx.z;
    const int warp = threadIdx.x >> 5;
    const int lane = threadIdx.x & 31;
    const int pos  = blockIdx.x * 8 + warp;
    if (pos >= g_cnt[z]) return;
    const int t = g_list[z][pos];

    const float* __restrict__ bias = (z == 0) ? b_hcw : b_roo;
    const float* Lrow = g_logits[z] + (size_t)pos * CDIM;
    const float4* L4 = reinterpret_cast<const float4*>(Lrow);
    const float4* B4 = reinterpret_cast<const float4*>(bias);

    float4 v[8];
    float mx = -1e30f;
    #pragma unroll
    for (int i = 0; i < 8; ++i) {
        float4 a = L4[lane + 32 * i];
        float4 b = B4[lane + 32 * i];
        a.x += b.x; a.y += b.y; a.z += b.z; a.w += b.w;
        v[i] = a;
        mx = fmaxf(mx, fmaxf(fmaxf(a.x, a.y), fmaxf(a.z, a.w)));
    }
    #pragma unroll
    for (int o = 16; o; o >>= 1) mx = fmaxf(mx, __shfl_xor_sync(0xffffffffu, mx, o));

    float sum = 0.f;
    #pragma unroll
    for (int i = 0; i < 8; ++i) {
        v[i].x = expf(v[i].x - mx); v[i].y = expf(v[i].y - mx);
        v[i].z = expf(v[i].z - mx); v[i].w = expf(v[i].w - mx);
        sum += (v[i].x + v[i].y) + (v[i].z + v[i].w);
    }
    #pragma unroll
    for (int o = 16; o; o >>= 1) sum += __shfl_xor_sync(0xffffffffu, sum, o);

    const float ne = g_nonend[t];
    const float scale = ne / sum;

    float* row = out + NTOK + (size_t)t * OUTW + ((z == 0) ? 2 : 2 + CDIM);
    #pragma unroll
    for (int i = 0; i < 8; ++i) {
        const int c0 = 4 * (lane + 32 * i);
        *reinterpret_cast<float2*>(row + c0)     = make_float2(v[i].x * scale, v[i].y * scale);
        *reinterpret_cast<float2*>(row + c0 + 2) = make_float2(v[i].z * scale, v[i].w * scale);
    }

    if (lane == 0) {
        const int yv = Y[t];
        int idx = yv - 2 - ((z == 0) ? 0 : CDIM);
        idx = min(max(idx, 0), CDIM - 1);
        const float li = Lrow[idx] + bias[idx];
        out[t] = (li - mx) - logf(sum) + logf(ne);
    }
}

// ---------------------------------------------------------------------------
// Launcher
// ---------------------------------------------------------------------------
extern "C" void kernel_launch(void* const* d_in, const int* in_sizes, int n_in,
                              void* d_out, int out_size)
{
    const float* X     = (const float*)d_in[0];
    const int*   pY    = (const int*)d_in[1];
    const int*   Y     = (const int*)d_in[2];
    const float* W_end = (const float*)d_in[3];
    const float* b_end = (const float*)d_in[4];
    const float* W_hcw = (const float*)d_in[5];
    const float* b_hcw = (const float*)d_in[6];
    const float* W_roo = (const float*)d_in[7];
    const float* b_roo = (const float*)d_in[8];
    float* out = (float*)d_out;
    (void)in_sizes; (void)n_in; (void)out_size;

    const int dyn = 128 + NSTAGE * STAGE_SZ;   // 196736
    static bool attr_set = false;
    if (!attr_set) {
        cudaFuncSetAttribute(k_gemm_mma, cudaFuncAttributeMaxDynamicSharedMemorySize, dyn);
        attr_set = true;
    }

    k_reset<<<1, 32>>>();
    k_classify<<<NTOK / 8, 256>>>(X, pY, W_end, b_end, out);
    k_convert_w_pad<<<dim3(2 * CDIM / 8 + 16, 2), 256>>>(W_hcw, W_roo);
    k_gemm_mma<<<dim3(CDIM / BN, NTOK / BM, 2), 256, dyn>>>();
    k_softmax<<<dim3(NTOK / 8, 1, 2), 256>>>(Y, b_hcw, b_roo, out);
}